// round 16
// baseline (speedup 1.0000x reference)
#include <cuda_runtime.h>
#include <cstdint>

#define BATCH   32
#define HW      3136
#define C       256
#define C4      64           // C/4
#define CR      64
#define PPC_G   16           // gap pixels per chunk
#define CH_G    196          // HW / PPC_G
#define PPC_M   64           // mul pixels per chunk (R2 geometry)
#define CH_M    49           // HW / PPC_M
#define NG      32           // channel groups of 8 floats

// Scratch (allocation-free per harness rules)
__device__ float g_partial[BATCH * CH_G * C];
__device__ float g_gate[BATCH * C];

// 256-bit load, pin line in L2 (evict_last) — R9's fastest gap load
__device__ __forceinline__ void ld256_evict_last(const float* p, uint32_t* u) {
    asm volatile("ld.global.nc.L2::evict_last.v8.b32 {%0,%1,%2,%3,%4,%5,%6,%7}, [%8];"
                 : "=r"(u[0]), "=r"(u[1]), "=r"(u[2]), "=r"(u[3]),
                   "=r"(u[4]), "=r"(u[5]), "=r"(u[6]), "=r"(u[7])
                 : "l"(p));
}

// ---------------------------------------------------------------------------
// gap_kernel: R9/R15 exact fastest configuration (18.6us, 5.77 TB/s).
// grid = (CH_G, BATCH) = 6272 blocks, 256 threads. evict_last v8 loads;
// plain partial store (keeps partials L2-resident for fc).
// ---------------------------------------------------------------------------
__global__ __launch_bounds__(256) void gap_kernel(const float* __restrict__ x)
{
    const int chunk = blockIdx.x;
    const int b     = blockIdx.y;
    const int tid   = threadIdx.x;
    const int c8    = tid & (NG - 1);
    const int pr    = tid >> 5;

    const float* xp = x + ((size_t)(b * HW + chunk * PPC_G + pr)) * C + c8 * 8;

    uint32_t u0[8], u1[8];
    ld256_evict_last(xp,                 u0);
    ld256_evict_last(xp + (size_t)8 * C, u1);

    __shared__ float red[8 * C];       // 8KB
    float* rp = &red[pr * C + c8 * 8];
#pragma unroll
    for (int k = 0; k < 8; ++k) {
        rp[k] = __uint_as_float(u0[k]) + __uint_as_float(u1[k]);
    }
    __syncthreads();

    float p0 = 0.0f;
#pragma unroll
    for (int g = 0; g < 8; ++g) {
        p0 += red[g * C + tid];
    }
    g_partial[(b * CH_G + chunk) * C + tid] = p0;
}

// ---------------------------------------------------------------------------
// fc_kernel: 32 blocks x 256 threads. 4-way accumulate over 196 partials
// (L2-hot), then squeeze->relu6->excite->hsigmoid -> gate.
// ---------------------------------------------------------------------------
__global__ __launch_bounds__(256) void fc_kernel(const float* __restrict__ w1,
                                                 const float* __restrict__ w2)
{
    const int b = blockIdx.x;
    const int t = threadIdx.x;

    __shared__ float s[C];
    __shared__ float h[CR];

    float s0 = 0.f, s1 = 0.f, s2 = 0.f, s3 = 0.f;
#pragma unroll
    for (int k = 0; k < CH_G; k += 4) {
        s0 += __ldg(&g_partial[(b * CH_G + k + 0) * C + t]);
        s1 += __ldg(&g_partial[(b * CH_G + k + 1) * C + t]);
        s2 += __ldg(&g_partial[(b * CH_G + k + 2) * C + t]);
        s3 += __ldg(&g_partial[(b * CH_G + k + 3) * C + t]);
    }
    s[t] = ((s0 + s1) + (s2 + s3)) * (1.0f / (float)HW);
    __syncthreads();

    if (t < CR) {
        float acc = 0.0f;
#pragma unroll 8
        for (int c = 0; c < C; ++c) {
            acc += s[c] * w1[c * CR + t];
        }
        h[t] = fminf(fmaxf(acc, 0.0f), 6.0f);
    }
    __syncthreads();

    float acc = 0.0f;
#pragma unroll
    for (int r = 0; r < CR; ++r) {
        acc += h[r] * w2[r * C + t];
    }
    g_gate[b * C + t] = fminf(fmaxf(acc + 3.0f, 0.0f), 6.0f) * (1.0f / 6.0f);
}

// ---------------------------------------------------------------------------
// mul_kernel: R2/R15 body with FULL LIFO ordering — both batch and chunk
// axes reversed, so mul's read sequence is the exact reverse of gap's write
// sequence. First reads consume the MRU tail of x still resident in L2 and
// walk backwards through the youngest surviving lines. __stcs out-writes are
// demoted so they minimally disturb residency.
// ---------------------------------------------------------------------------
__global__ __launch_bounds__(256) void mul_kernel(const float4* __restrict__ x4,
                                                  float4* __restrict__ out4)
{
    const int chunk = (CH_M - 1) - blockIdx.x;    // reversed chunk order
    const int b     = (BATCH - 1) - blockIdx.y;   // reversed batch order
    const int tid   = threadIdx.x;
    const int c4    = tid & (C4 - 1);
    const int pr    = tid >> 6;

    const float4 gv = __ldg(&((const float4*)g_gate)[b * C4 + c4]);

    const size_t base = ((size_t)(b * HW + chunk * PPC_M + pr)) * C4 + c4;

#pragma unroll
    for (int p = (PPC_M / 4) - 1; p >= 0; --p) {  // 16 iterations, reversed
        size_t idx = base + (size_t)p * 4 * C4;
        float4 v = x4[idx];
        v.x *= gv.x; v.y *= gv.y; v.z *= gv.z; v.w *= gv.w;
        __stcs(&out4[idx], v);
    }
}

extern "C" void kernel_launch(void* const* d_in, const int* in_sizes, int n_in,
                              void* d_out, int out_size) {
    const float* x  = (const float*)d_in[0];
    const float* w1 = (const float*)d_in[1];
    const float* w2 = (const float*)d_in[2];
    float* out      = (float*)d_out;

    dim3 ggrid(CH_G, BATCH);
    gap_kernel<<<ggrid, 256>>>(x);
    fc_kernel<<<BATCH, 256>>>(w1, w2);
    dim3 mgrid(CH_M, BATCH);
    mul_kernel<<<mgrid, 256>>>((const float4*)x, (float4*)out);
}

// round 17
// speedup vs baseline: 1.0068x; 1.0068x over previous
#include <cuda_runtime.h>
#include <cstdint>

#define BATCH   32
#define HW      3136
#define C       256
#define C4      64           // C/4
#define CR      64
#define PPC_G   16           // gap pixels per chunk
#define CH_G    196          // HW / PPC_G
#define PPC_M   64           // mul pixels per chunk
#define CH_M    49           // HW / PPC_M
#define NG      32           // channel groups of 8 floats

// Scratch (allocation-free per harness rules)
__device__ float g_partial[BATCH * CH_G * C];
__device__ float g_gate[BATCH * C];

// 256-bit load, pin line in L2 (evict_last) — R9's fastest gap load
__device__ __forceinline__ void ld256_evict_last(const float* p, uint32_t* u) {
    asm volatile("ld.global.nc.L2::evict_last.v8.b32 {%0,%1,%2,%3,%4,%5,%6,%7}, [%8];"
                 : "=r"(u[0]), "=r"(u[1]), "=r"(u[2]), "=r"(u[3]),
                   "=r"(u[4]), "=r"(u[5]), "=r"(u[6]), "=r"(u[7])
                 : "l"(p));
}

// ---------------------------------------------------------------------------
// gap_kernel: R9/R15 exact fastest configuration (18.6us best, 5.77 TB/s).
// grid = (CH_G, BATCH) = 6272 blocks, 256 threads. evict_last v8 loads;
// plain partial store (keeps partials L2-resident for fc).
// ---------------------------------------------------------------------------
__global__ __launch_bounds__(256) void gap_kernel(const float* __restrict__ x)
{
    const int chunk = blockIdx.x;
    const int b     = blockIdx.y;
    const int tid   = threadIdx.x;
    const int c8    = tid & (NG - 1);
    const int pr    = tid >> 5;

    const float* xp = x + ((size_t)(b * HW + chunk * PPC_G + pr)) * C + c8 * 8;

    uint32_t u0[8], u1[8];
    ld256_evict_last(xp,                 u0);
    ld256_evict_last(xp + (size_t)8 * C, u1);

    __shared__ float red[8 * C];       // 8KB
    float* rp = &red[pr * C + c8 * 8];
#pragma unroll
    for (int k = 0; k < 8; ++k) {
        rp[k] = __uint_as_float(u0[k]) + __uint_as_float(u1[k]);
    }
    __syncthreads();

    float p0 = 0.0f;
#pragma unroll
    for (int g = 0; g < 8; ++g) {
        p0 += red[g * C + tid];
    }
    g_partial[(b * CH_G + chunk) * C + tid] = p0;
}

// ---------------------------------------------------------------------------
// fc_kernel: 32 blocks x 256 threads. 4-way accumulate over 196 partials
// (L2-hot), then squeeze->relu6->excite->hsigmoid -> gate.
// ---------------------------------------------------------------------------
__global__ __launch_bounds__(256) void fc_kernel(const float* __restrict__ w1,
                                                 const float* __restrict__ w2)
{
    const int b = blockIdx.x;
    const int t = threadIdx.x;

    __shared__ float s[C];
    __shared__ float h[CR];

    float s0 = 0.f, s1 = 0.f, s2 = 0.f, s3 = 0.f;
#pragma unroll
    for (int k = 0; k < CH_G; k += 4) {
        s0 += __ldg(&g_partial[(b * CH_G + k + 0) * C + t]);
        s1 += __ldg(&g_partial[(b * CH_G + k + 1) * C + t]);
        s2 += __ldg(&g_partial[(b * CH_G + k + 2) * C + t]);
        s3 += __ldg(&g_partial[(b * CH_G + k + 3) * C + t]);
    }
    s[t] = ((s0 + s1) + (s2 + s3)) * (1.0f / (float)HW);
    __syncthreads();

    if (t < CR) {
        float acc = 0.0f;
#pragma unroll 8
        for (int c = 0; c < C; ++c) {
            acc += s[c] * w1[c * CR + t];
        }
        h[t] = fminf(fmaxf(acc, 0.0f), 6.0f);
    }
    __syncthreads();

    float acc = 0.0f;
#pragma unroll
    for (int r = 0; r < CR; ++r) {
        acc += h[r] * w2[r * C + t];
    }
    g_gate[b * C + t] = fminf(fmaxf(acc + 3.0f, 0.0f), 6.0f) * (1.0f / 6.0f);
}

// ---------------------------------------------------------------------------
// mul_kernel: R4's 8-deep batched shape (best measured per-byte rate) +
// R15's reversed batch order. Two half-passes of [8 loads] -> [8 mul+stcs]:
// long same-direction bursts minimize DRAM read/write turnaround vs the
// interleaved load-store-load-store pattern.
// ---------------------------------------------------------------------------
__global__ __launch_bounds__(256) void mul_kernel(const float4* __restrict__ x4,
                                                  float4* __restrict__ out4)
{
    const int chunk = blockIdx.x;
    const int b     = (BATCH - 1) - blockIdx.y;   // reversed batch order
    const int tid   = threadIdx.x;
    const int c4    = tid & (C4 - 1);
    const int pr    = tid >> 6;

    const float4 gv = __ldg(&((const float4*)g_gate)[b * C4 + c4]);
    const size_t base = ((size_t)(b * HW + chunk * PPC_M + pr)) * C4 + c4;

#pragma unroll
    for (int half = 0; half < 2; ++half) {
        float4 v[8];
#pragma unroll
        for (int i = 0; i < 8; ++i) {              // 8 loads in flight
            v[i] = __ldcg(&x4[base + (size_t)(half * 8 + i) * 4 * C4]);
        }
#pragma unroll
        for (int i = 0; i < 8; ++i) {              // 8 stores back-to-back
            v[i].x *= gv.x; v[i].y *= gv.y; v[i].z *= gv.z; v[i].w *= gv.w;
            __stcs(&out4[base + (size_t)(half * 8 + i) * 4 * C4], v[i]);
        }
    }
}

extern "C" void kernel_launch(void* const* d_in, const int* in_sizes, int n_in,
                              void* d_out, int out_size) {
    const float* x  = (const float*)d_in[0];
    const float* w1 = (const float*)d_in[1];
    const float* w2 = (const float*)d_in[2];
    float* out      = (float*)d_out;

    dim3 ggrid(CH_G, BATCH);
    gap_kernel<<<ggrid, 256>>>(x);
    fc_kernel<<<BATCH, 256>>>(w1, w2);
    dim3 mgrid(CH_M, BATCH);
    mul_kernel<<<mgrid, 256>>>((const float4*)x, (float4*)out);
}